// round 3
// baseline (speedup 1.0000x reference)
#include <cuda_runtime.h>
#include <cuda_bf16.h>

#define FULL 0xffffffffu
#define NEGV -1000000000.0f

// Problem shape (fixed by setup_inputs): B=64, N=128, L=32
#define BB   64
#define NN_  128
#define LL   32
#define NN2  (NN_ * NN_)          /* 16384 cells per batch   */
#define CELLS (BB * NN2)          /* 1,048,576 total cells   */
#define K1_CPB 16                 /* cells per K1 block      */
#define K1_BLOCKS (CELLS / K1_CPB)        /* 65536           */
#define PARTS (NN2 / K1_CPB)              /* 1024 per batch  */
#define BP   136                  /* beta row pitch: 136 % 32 == 8 -> conflict-free */

// ---------------- device scratch (no allocations allowed) ----------------
__device__ float g_pot[CELLS];            // 4 MB: label-maxed span potentials
__device__ float g_goldpart[BB * PARTS];  // 256 KB: per-block gold partial sums
__device__ float g_margin[BB];
__device__ int   g_lab64;                 // labels dtype flag (1 = int64)

__device__ __forceinline__ int load_label(const void* labels, int idx) {
    return g_lab64 ? (int)((const long long*)labels)[idx]
                   : ((const int*)labels)[idx];
}

// ---------------- K0: detect labels dtype (int32 vs int64) ----------------
// If the buffer really is int64, every 8-byte word is a small value in
// [-100, 32). If it is int32 (random 0..31), the high halves are almost
// surely nonzero, so the int64 interpretation fails the range check.
__global__ void k_detect(const void* __restrict__ labels) {
    const long long* p = (const long long*)labels;
    long long v = p[threadIdx.x];
    int bad = (v < -100 || v >= 32) ? 1 : 0;
    int nbad = __syncthreads_count(bad);
    if (threadIdx.x == 0) g_lab64 = (nbad == 0) ? 1 : 0;
}

// ---------------- K1: pot[b,i,j] + gold partial sums ----------------
// One warp per 2 cells; lane == label index (L == 32).
// pot = max_l (logit_l - logit_0 + (l == gold ? 0 : 1))   (margin augment)
// gold contribution = logit_gold - logit_0
// The special -1e9 augment on (b, 0, len-1, 0) is applied in K2.
__global__ void __launch_bounds__(256) k1_pot(const float* __restrict__ logits,
                                              const void* __restrict__ labels) {
    const int warp = threadIdx.x >> 5;
    const int lane = threadIdx.x & 31;
    const int c0 = (blockIdx.x * 8 + warp) * 2;
    __shared__ float sh[K1_CPB];

    const float* base = logits + (size_t)c0 * LL;
    float x0 = base[lane];
    float x1 = base[LL + lane];
    int g0 = load_label(labels, c0);     if (g0 < 0) g0 = 0;
    int g1 = load_label(labels, c0 + 1); if (g1 < 0) g1 = 0;

    float m00 = __shfl_sync(FULL, x0, 0);
    float m01 = __shfl_sync(FULL, x1, 0);
    float d0 = x0 - m00, d1 = x1 - m01;        // logits - logits[...,0]
    float p0 = d0 + (lane == g0 ? 0.0f : 1.0f);
    float p1 = d1 + (lane == g1 ? 0.0f : 1.0f);
#pragma unroll
    for (int o = 16; o > 0; o >>= 1) {
        p0 = fmaxf(p0, __shfl_xor_sync(FULL, p0, o));
        p1 = fmaxf(p1, __shfl_xor_sync(FULL, p1, o));
    }
    float gold0 = __shfl_sync(FULL, d0, g0);
    float gold1 = __shfl_sync(FULL, d1, g1);

    if (lane == 0) {
        g_pot[c0]     = p0;
        g_pot[c0 + 1] = p1;
        sh[warp * 2]     = gold0;
        sh[warp * 2 + 1] = gold1;
    }
    __syncthreads();
    if (threadIdx.x == 0) {
        float s = 0.0f;
#pragma unroll
        for (int t = 0; t < K1_CPB; ++t) s += sh[t];   // fixed order -> deterministic
        g_goldpart[blockIdx.x] = s;                     // blockIdx = b*PARTS + local
    }
}

// ---------------- K2: per-batch max-plus CKY ----------------
// beta[i][w] = best score of span [i, i+w].
// beta[i][w] = pot[i][i+w] + max_{k<w} beta[i][k] + beta[i+k+1][w-1-k]
// 1024 threads: i = tid>>3, kg = tid&7 (8-way split of k, shfl-reduced).
// Row pitch BP=136 (== 8 mod 32) makes both operand patterns bank-conflict-free.
__global__ void __launch_bounds__(1024) k2_cky(const float* __restrict__ logits,
                                               const void* __restrict__ labels) {
    extern __shared__ float beta[];   // NN_ * BP floats = 69,632 B
    __shared__ float red[1024];
    const int b = blockIdx.x;
    const int tid = threadIdx.x;

    // ---- sequence length: count(labels[b,0,:] != -100) ----
    int pflag = 0;
    if (tid < NN_) {
        int lab = load_label(labels, b * NN2 + tid);
        pflag = (lab != -100);
    }
    int len = __syncthreads_count(pflag);

    // ---- deterministic gold reduction (1024 partials) ----
    red[tid] = g_goldpart[b * PARTS + tid];
    __syncthreads();
#pragma unroll
    for (int s = 512; s > 0; s >>= 1) {
        if (tid < s) red[tid] += red[tid + s];
        __syncthreads();
    }
    float gold = red[0];

    // ---- recompute pot[b,0,len-1] with the -1e9 augment on label 0 ----
    if (tid < 32) {
        int j = len - 1;
        int g = load_label(labels, b * NN2 + j); if (g < 0) g = 0;
        float x = logits[((size_t)b * NN2 + (size_t)j) * LL + tid];
        float m0 = __shfl_sync(FULL, x, 0);
        float cand = (x - m0) + (tid == g ? 0.0f : 1.0f)
                              + (tid == 0 ? NEGV : 0.0f);
#pragma unroll
        for (int o = 16; o > 0; o >>= 1)
            cand = fmaxf(cand, __shfl_xor_sync(FULL, cand, o));
        if (tid == 0) g_pot[b * NN2 + j] = cand;
    }
    __syncthreads();   // order special-cell gmem write before any pot read

    // ---- width 0: diagonal terms ----
    const float* potb = g_pot + b * NN2;
    if (tid < NN_) beta[tid * BP] = potb[tid * (NN_ + 1)];
    __syncthreads();

    const int i  = tid >> 3;
    const int kg = tid & 7;

    for (int w = 1; w < NN_; ++w) {
        float acc = -1e30f;
        if (i < NN_ - w) {
            int aL = i * BP + kg;                     // beta[i][k]
            int aR = (i + kg + 1) * BP + (w - 1 - kg);// beta[i+k+1][w-1-k]
#pragma unroll 4
            for (int k = kg; k < w; k += 8) {
                acc = fmaxf(acc, beta[aL] + beta[aR]);
                aL += 8;
                aR += 8 * BP - 8;
            }
        }
        // reduce the 8 k-groups (all lanes participate -> full-mask safe)
        acc = fmaxf(acc, __shfl_xor_sync(FULL, acc, 4));
        acc = fmaxf(acc, __shfl_xor_sync(FULL, acc, 2));
        acc = fmaxf(acc, __shfl_xor_sync(FULL, acc, 1));
        if (kg == 0 && i < NN_ - w)
            beta[i * BP + w] = acc + __ldg(&potb[i * NN_ + i + w]);
        __syncthreads();
    }

    if (tid == 0) {
        float pred = beta[len - 1];          // beta[0][len-1]
        g_margin[b] = fmaxf(pred - gold, 0.0f);
    }
}

// ---------------- K3: mean over batch ----------------
__global__ void k3_mean(float* __restrict__ out) {
    __shared__ float s[64];
    int t = threadIdx.x;
    s[t] = g_margin[t];
    __syncthreads();
#pragma unroll
    for (int st = 32; st > 0; st >>= 1) {
        if (t < st) s[t] += s[t + st];
        __syncthreads();
    }
    if (t == 0) out[0] = s[0] * (1.0f / 64.0f);
}

// ---------------- launch ----------------
extern "C" void kernel_launch(void* const* d_in, const int* in_sizes, int n_in,
                              void* d_out, int out_size) {
    const float* logits = (const float*)d_in[0];
    const void*  labels = d_in[1];

    // 68 KB dynamic smem for K2 (idempotent; legal outside stream capture scope)
    cudaFuncSetAttribute(k2_cky, cudaFuncAttributeMaxDynamicSharedMemorySize,
                         NN_ * BP * (int)sizeof(float));

    k_detect<<<1, 256>>>(labels);
    k1_pot<<<K1_BLOCKS, 256>>>(logits, labels);
    k2_cky<<<BB, 1024, NN_ * BP * (int)sizeof(float)>>>(logits, labels);
    k3_mean<<<1, 64>>>((float*)d_out);
}

// round 4
// speedup vs baseline: 1.5418x; 1.5418x over previous
#include <cuda_runtime.h>
#include <cuda_bf16.h>

#define FULL 0xffffffffu
#define NEGV -1000000000.0f

// Problem shape (fixed by setup_inputs): B=64, N=128, L=32
#define BB    64
#define NN_   128
#define LL    32
#define NN2   (NN_ * NN_)            /* 16384 cells per batch */
#define CELLS (BB * NN2)             /* 1,048,576 cells        */
#define K1_CPW 4                     /* cells per warp in K1   */
#define K1_CPB 32                    /* cells per K1 block     */
#define K1_BLOCKS (CELLS / K1_CPB)   /* 32768                  */
#define PARTS (NN2 / K1_CPB)         /* 512 gold partials per batch */
#define BP    132                    /* beta pitch: 132 % 32 == 4 -> conflict-free */

// ---------------- device scratch (no allocations allowed) ----------------
__device__ float g_potd[CELLS];           // diag-major pot: [b][w*128 + i], upper triangle only
__device__ float g_goldpart[BB * PARTS];  // per-block gold partial sums
__device__ float g_margin[BB];
__device__ unsigned g_count;              // wrapping completion counter (resets each replay)

// float -> monotonic u32 key (and back) so we can use redux.sync.max.u32
__device__ __forceinline__ unsigned f2key(float x) {
    int i = __float_as_int(x);
    return (unsigned)i ^ ((unsigned)(i >> 31) | 0x80000000u);
}
__device__ __forceinline__ float key2f(unsigned k) {
    unsigned u = (k & 0x80000000u) ? (k ^ 0x80000000u) : ~k;
    return __int_as_float((int)u);
}

// ---------------- K1: pot (diag-major, upper tri) + gold partials ----------------
// One warp per 4 cells; lane == label (L == 32). Per cell:
//   d    = logit[l] - logit[0]
//   pot  = max_l ( d + (l == gold ? 0 : 1) )      (margin augment)
//   gold = d[gold]
// The -1e9 augment on (b,0,len-1,0) is applied later in K2 (smem, cheap).
__global__ void __launch_bounds__(256) k1_pot(const float* __restrict__ logits,
                                              const void* __restrict__ labels) {
    const int warp = threadIdx.x >> 5;
    const int lane = threadIdx.x & 31;

    // per-warp labels dtype detection (uniform, deterministic):
    // interpret first 32 8-byte words as int64; valid labels lie in [-100, 32)
    long long v = ((const long long*)labels)[lane];
    const bool lab64 = (__ballot_sync(FULL, v >= -100 && v < 32) == FULL);

    const int c0 = (blockIdx.x * 8 + warp) * K1_CPW;
    float golds = 0.0f;

#pragma unroll
    for (int q = 0; q < K1_CPW; ++q) {
        const int c = c0 + q;
        float x = logits[(size_t)c * LL + lane];
        int g = lab64 ? (int)((const long long*)labels)[c]
                      : ((const int*)labels)[c];
        if (g < 0) g = 0;
        float m0 = __shfl_sync(FULL, x, 0);
        float d  = x - m0;
        unsigned kmax = __reduce_max_sync(FULL, f2key(d + (lane == g ? 0.0f : 1.0f)));
        golds += __shfl_sync(FULL, d, g);
        if (lane == 0) {
            int jj = c & 127;
            int ii = (c >> 7) & 127;
            if (jj >= ii) {
                int b = c >> 14;
                g_potd[((size_t)b << 14) + ((jj - ii) << 7) + ii] = key2f(kmax);
            }
        }
    }

    __shared__ float sh[8];
    if (lane == 0) sh[warp] = golds;
    __syncthreads();
    if (threadIdx.x == 0) {
        float s = 0.0f;
#pragma unroll
        for (int t = 0; t < 8; ++t) s += sh[t];   // fixed order -> deterministic
        g_goldpart[blockIdx.x] = s;               // blockIdx = b*PARTS + local
    }
}

// ---------------- K2: per-batch max-plus CKY, all in smem ----------------
// beta[i][w] = potS[w][i] + max_{k<w} beta[i][k] + beta[i+k+1][w-1-k]
// 512 threads: i = tid>>2, kg = tid&3 (4-way k split, 2-shfl reduce).
// Pitch BP=132 (== 4 mod 32): both LDS patterns are conflict-free.
// Last finishing block reduces g_margin in fixed order -> deterministic mean.
__global__ void __launch_bounds__(512) k2_cky(const float* __restrict__ logits,
                                              const void* __restrict__ labels,
                                              float* __restrict__ out) {
    extern __shared__ float smem[];
    float* beta = smem;               // NN_ * BP floats = 67,584 B
    float* potS = smem + NN_ * BP;    // NN_ * NN_ floats = 65,536 B
    __shared__ float red[512];

    const int b = blockIdx.x;
    const int tid = threadIdx.x;

    // labels dtype detection (per-warp, uniform)
    long long v = ((const long long*)labels)[tid & 31];
    const bool lab64 = (__ballot_sync(FULL, v >= -100 && v < 32) == FULL);

    // sequence length = count(labels[b,0,:] != -100)
    int pflag = 0;
    if (tid < NN_) {
        size_t idx = ((size_t)b << 14) + tid;
        int lab = lab64 ? (int)((const long long*)labels)[idx]
                        : ((const int*)labels)[idx];
        pflag = (lab != -100);
    }
    const int len = __syncthreads_count(pflag);

    // stage pot plane (diag-major) into smem, coalesced float4
    {
        const float4* src = (const float4*)(g_potd + ((size_t)b << 14));
        float4* dst = (float4*)potS;
#pragma unroll
        for (int t = 0; t < 8; ++t) dst[tid + t * 512] = src[tid + t * 512];
    }

    // gold partials -> fixed-order tree reduce
    red[tid] = g_goldpart[b * PARTS + tid];
    __syncthreads();                               // also fences potS staging
#pragma unroll
    for (int s = 256; s > 0; s >>= 1) {
        if (tid < s) red[tid] += red[tid + s];
        __syncthreads();
    }

    // recompute pot[b,0,len-1] with the extra -1e9 augment on label 0
    if (tid < 32) {
        const int j = len - 1;
        size_t cell = ((size_t)b << 14) + j;
        int g = lab64 ? (int)((const long long*)labels)[cell]
                      : ((const int*)labels)[cell];
        if (g < 0) g = 0;
        float x  = logits[cell * LL + tid];
        float m0 = __shfl_sync(FULL, x, 0);
        float cand = (x - m0) + (tid == g ? 0.0f : 1.0f)
                              + (tid == 0 ? NEGV : 0.0f);
#pragma unroll
        for (int o = 16; o > 0; o >>= 1)
            cand = fmaxf(cand, __shfl_xor_sync(FULL, cand, o));
        if (tid == 0) potS[(size_t)j * NN_ + 0] = cand;   // potS[w=len-1][i=0]
    }
    __syncthreads();

    // width 0: diagonal terms
    if (tid < NN_) beta[tid * BP] = potS[tid];            // potS[0][i]
    __syncthreads();

    const int i  = tid >> 2;
    const int kg = tid & 3;
    const int rstep = 4 * BP - 4;

    for (int w = 1; w < NN_; ++w) {
        float acc0 = -1e30f, acc1 = -1e30f;
        if (i < NN_ - w) {
            const float* pL = beta + i * BP + kg;               // beta[i][k]
            const float* pR = beta + (i + kg + 1) * BP + (w - 1 - kg); // beta[i+k+1][w-1-k]
            int t = (w - kg + 3) >> 2;                          // k = kg, kg+4, ... < w
            while (t >= 2) {
                acc0 = fmaxf(acc0, pL[0] + pR[0]);
                acc1 = fmaxf(acc1, pL[4] + pR[rstep]);
                pL += 8; pR += 2 * rstep;
                t -= 2;
            }
            if (t) acc0 = fmaxf(acc0, pL[0] + pR[0]);
        }
        float acc = fmaxf(acc0, acc1);
        acc = fmaxf(acc, __shfl_xor_sync(FULL, acc, 1));
        acc = fmaxf(acc, __shfl_xor_sync(FULL, acc, 2));
        if (kg == 0 && i < NN_ - w)
            beta[i * BP + w] = acc + potS[w * NN_ + i];
        __syncthreads();
    }

    if (tid == 0) {
        float pred = beta[len - 1];                 // beta[0][len-1]
        g_margin[b] = fmaxf(pred - red[0], 0.0f);
        __threadfence();
        unsigned old = atomicInc(&g_count, BB - 1); // wraps to 0 -> replay-safe
        if (old == BB - 1) {                        // last block: fixed-order mean
            float s = 0.0f;
            volatile float* gm = g_margin;
#pragma unroll
            for (int t = 0; t < BB; ++t) s += gm[t];
            out[0] = s * (1.0f / (float)BB);
        }
    }
}

// ---------------- launch ----------------
extern "C" void kernel_launch(void* const* d_in, const int* in_sizes, int n_in,
                              void* d_out, int out_size) {
    const float* logits = (const float*)d_in[0];
    const void*  labels = d_in[1];

    const int smem_bytes = (NN_ * BP + NN_ * NN_) * (int)sizeof(float); // 133,120
    cudaFuncSetAttribute(k2_cky, cudaFuncAttributeMaxDynamicSharedMemorySize, smem_bytes);

    k1_pot<<<K1_BLOCKS, 256>>>(logits, labels);
    k2_cky<<<BB, 512, smem_bytes>>>(logits, labels, (float*)d_out);
}